// round 10
// baseline (speedup 1.0000x reference)
#include <cuda_runtime.h>
#include <cstdint>

// D3PM q_sample — bit-exact vs JAX threefry, partitionable mode:
//   split:  key_i = (o0, o1) of threefry2x32((0,42), (0, i))     [foldlike]
//   bits32: bits[i] = o0 ^ o1 of threefry2x32(key, (0, flat_idx)),
//           flat_idx row-major over (B, L, N).
//
// Output (float32): [0,R) noised_structure, [R,2R) noised_sequence, [2R,2R+B) t.
//
// Pruning theorem (exact): argmax of gumbel+logits is ALWAYS x0 or MASK
// (other channels capped at log(1e-10)+g_max = -7.086 < -5.163 <= best of
// {x0,MASK}), so 2 RNG draws per element suffice. Ties -> lower class index.
//
// Single fused kernel:
//  - structure vs sequence disambiguated per block by warp 0 (ballot on v>32
//    over 16 elements each; sequence <= 32 always).
//  - t vs alpha bound on host by size divisibility (|t| divides B*L).
//  - log(a+eps), log((1-a)+eps) computed ONCE per block into smem (blocks are
//    256-aligned; L % 256 == 0 and R % 256 == 0 make them block-uniform).
//    Bit-exact: identical fp32 inputs -> identical libdevice logf outputs.

#define TINYF 1.17549435e-38f
#define EPSF  1e-10f

__host__ __device__ __forceinline__ unsigned rotl32(unsigned x, int r) {
#ifdef __CUDA_ARCH__
    return __funnelshift_l(x, x, r);
#else
    return (x << r) | (x >> (32 - r));
#endif
}

// Standard threefry2x32, 20 rounds (matches jax/_src/prng.py lowering).
__host__ __device__ __forceinline__ void threefry2x32(
    unsigned k0, unsigned k1, unsigned m0, unsigned m1,
    unsigned& o0, unsigned& o1)
{
    const unsigned ks2 = 0x1BD11BDAu ^ k0 ^ k1;
    unsigned x0 = m0 + k0;
    unsigned x1 = m1 + k1;
#define TF_R(r) { x0 += x1; x1 = rotl32(x1, (r)) ^ x0; }
    TF_R(13) TF_R(15) TF_R(26) TF_R(6)
    x0 += k1;  x1 += ks2 + 1u;
    TF_R(17) TF_R(29) TF_R(16) TF_R(24)
    x0 += ks2; x1 += k0 + 2u;
    TF_R(13) TF_R(15) TF_R(26) TF_R(6)
    x0 += k0;  x1 += k1 + 3u;
    TF_R(17) TF_R(29) TF_R(16) TF_R(24)
    x0 += k1;  x1 += ks2 + 4u;
    TF_R(13) TF_R(15) TF_R(26) TF_R(6)
    x0 += ks2; x1 += k0 + 5u;
#undef TF_R
    o0 = x0; o1 = x1;
}

// Partitionable 32-bit stream at flat index i: o0 ^ o1 of F(key, (0, i)).
__device__ __forceinline__ unsigned jax_bits32(unsigned ka, unsigned kb, unsigned i) {
    unsigned o0, o1;
    threefry2x32(ka, kb, 0u, i, o0, o1);
    return o0 ^ o1;
}

// JAX gumbel: u = bitcast((bits>>9)|0x3f800000)-1; f = max(tiny, u*(1-tiny)+tiny)
// ((1-tiny) rounds to 1.0f); g = -log(-log(f)). libdevice logf == XLA's log.
__device__ __forceinline__ float gumbel_from_bits(unsigned bits) {
    float u = __uint_as_float(0x3f800000u | (bits >> 9)) - 1.0f;
    float f = fmaxf(TINYF, u + TINYF);
    return -logf(-logf(f));
}

__device__ __forceinline__ float sample_row(
    int row, int x0, float la, float lm,
    unsigned ka, unsigned kb, int N, int MASK)
{
    if (x0 == MASK) return (float)x0;   // combined channel always wins
    unsigned b1 = jax_bits32(ka, kb, (unsigned)row * (unsigned)N + (unsigned)x0);
    unsigned b2 = jax_bits32(ka, kb, (unsigned)row * (unsigned)N + (unsigned)MASK);
    float vx = gumbel_from_bits(b1) + la;
    float vm = gumbel_from_bits(b2) + lm;
    if (vx > vm) return (float)x0;
    if (vm > vx) return (float)MASK;
    return (float)((x0 < MASK) ? x0 : MASK);   // argmax first-max tie-break
}

__global__ __launch_bounds__(256)
void d3pm_fused_kernel(const int* __restrict__ pA, const int* __restrict__ pB,
                       const int* __restrict__ t, const float* __restrict__ alpha,
                       float* __restrict__ out,
                       unsigned ksa, unsigned ksb,
                       unsigned kqa, unsigned kqb,
                       int rows, int Bv, int shift, int L, int aligned)
{
    __shared__ float s_la, s_lm;
    __shared__ int   s_swap;

    const int tid = threadIdx.x;
    const int j0  = blockIdx.x * 256;

    // warp 0: which big array is structure? (sequence values are always <= 32;
    // structure ~U[0,516) exceeds 32 among 16 samples w.p. 1 - 8e-20)
    if (tid < 32) {
        int lane = tid;
        int v = (lane < 16) ? pA[lane] : pB[lane - 16];
        unsigned big = __ballot_sync(0xffffffffu, v > 32);
        if (lane == 0) s_swap = ((big & 0xFFFFu) == 0u) ? 1 : 0;
    }
    // warp 1: block-uniform log(a+eps), log((1-a)+eps) (aligned case).
    else if (tid >= 32 && tid < 34 && aligned) {
        int seg = (j0 < rows) ? 0 : 1;     // passthrough blocks guarded below
        int r0  = j0 - (seg ? rows : 0);
        if (j0 < 2 * rows) {
            int batch = r0 >> shift;
            float a = alpha[t[batch]];
            if (tid == 32) s_la = logf(a + EPSF);
            else           s_lm = logf((1.0f - a) + EPSF);
        }
    }
    __syncthreads();

    const int j = j0 + tid;
    if (j >= 2 * rows + Bv) return;

    const int* structure = s_swap ? pB : pA;
    const int* sequence  = s_swap ? pA : pB;

    float la, lm;
    if (aligned) { la = s_la; lm = s_lm; }
    else {
        int r = (j < rows) ? j : j - rows;
        if (j < 2 * rows) {
            int batch = (shift >= 0) ? (r >> shift) : (r / L);
            float a = alpha[t[batch]];
            la = logf(a + EPSF);
            lm = logf((1.0f - a) + EPSF);
        } else { la = 0.0f; lm = 0.0f; }
    }

    if (j < rows) {
        out[j] = sample_row(j, structure[j], la, lm, ksa, ksb, 516, 3);
    } else if (j < 2 * rows) {
        int r = j - rows;
        out[j] = sample_row(r, sequence[r], la, lm, kqa, kqb, 33, 32);
    } else {
        out[j] = (float)t[j - 2 * rows];
    }
}

extern "C" void kernel_launch(void* const* d_in, const int* in_sizes, int n_in,
                              void* d_out, int out_size)
{
    // Bind by size: two largest (equal) = structure/sequence candidates
    // (disambiguated on-device); of the two small ones, t's size divides
    // rows (= B, and B | B*L) while alpha's (T+1 = 501) does not.
    int idx[4] = {0, 1, 2, 3};
    for (int i = 0; i < 3; i++)
        for (int k = i + 1; k < 4; k++)
            if (in_sizes[idx[k]] > in_sizes[idx[i]]) {
                int tmp = idx[i]; idx[i] = idx[k]; idx[k] = tmp;
            }
    const int iA = idx[0], iB = idx[1];
    int iT = idx[3], iAl = idx[2];
    const int rows = in_sizes[iA];
    if (rows % in_sizes[iT] != 0 && rows % in_sizes[iAl] == 0) {
        int tmp = iT; iT = iAl; iAl = tmp;
    }

    const int*   pA    = (const int*)  d_in[iA];
    const int*   pB    = (const int*)  d_in[iB];
    const int*   t     = (const int*)  d_in[iT];
    const float* alpha = (const float*)d_in[iAl];
    const int    Bv    = in_sizes[iT];
    const int    L     = rows / Bv;

    int shift = -1;
    if ((L & (L - 1)) == 0) { shift = 0; while ((1 << shift) < L) shift++; }
    const int aligned = (shift >= 0) && (rows % 256 == 0) && (L % 256 == 0);

    // key = jax.random.key(42) -> (0, 42)
    // partitionable (foldlike) split: key_i = (o0, o1) of F((0,42), (0, i))
    unsigned ksa, ksb, kqa, kqb;
    threefry2x32(0u, 42u, 0u, 0u, ksa, ksb);   // ks (structure)
    threefry2x32(0u, 42u, 0u, 1u, kqa, kqb);   // kq (sequence)

    const int total   = 2 * rows + Bv;
    const int blocks  = (total + 255) / 256;

    d3pm_fused_kernel<<<blocks, 256>>>(
        pA, pB, t, alpha, (float*)d_out,
        ksa, ksb, kqa, kqb, rows, Bv, shift, L, aligned);
}

// round 11
// speedup vs baseline: 1.3375x; 1.3375x over previous
#include <cuda_runtime.h>
#include <cstdint>

// D3PM q_sample — bit-exact vs JAX threefry, partitionable mode:
//   split:  key_i = (o0, o1) of threefry2x32((0,42), (0, i))     [foldlike]
//   bits32: bits[i] = o0 ^ o1 of threefry2x32(key, (0, flat_idx)),
//           flat_idx row-major over (B, L, N).
//
// Output (float32): [0,R) noised_structure, [R,2R) noised_sequence, [2R,2R+B) t.
//
// Pruning theorem (exact): argmax of gumbel+logits is ALWAYS x0 or MASK, so 2
// RNG draws per element suffice. Ties -> lower class index. Comparison path is
// bit-identical to the reference (one flipped token would already exceed the
// 1e-3 rel-err budget).
//
// R10 lesson: no barriers / no block-uniform prologue in the hot kernel — the
// t->alpha->logf chain must overlap with threefry. So: a tiny aux kernel
// (a) ballot-detects which big input is `structure' (sequence <= 32 always),
// (b) tabulates la[v]=logf(alpha[v]+eps), lm[v]=logf((1-alpha[v])+eps) for all
// 501 t-values. The hot kernel then needs zero logf for logits and no syncs;
// each thread handles 2 elements for ILP.

#define TINYF 1.17549435e-38f
#define EPSF  1e-10f
#define TMAX_TAB 4096

__device__ int   g_swap;
__device__ float g_la[TMAX_TAB];
__device__ float g_lm[TMAX_TAB];

__host__ __device__ __forceinline__ unsigned rotl32(unsigned x, int r) {
#ifdef __CUDA_ARCH__
    return __funnelshift_l(x, x, r);
#else
    return (x << r) | (x >> (32 - r));
#endif
}

// Standard threefry2x32, 20 rounds (matches jax/_src/prng.py lowering).
__host__ __device__ __forceinline__ void threefry2x32(
    unsigned k0, unsigned k1, unsigned m0, unsigned m1,
    unsigned& o0, unsigned& o1)
{
    const unsigned ks2 = 0x1BD11BDAu ^ k0 ^ k1;
    unsigned x0 = m0 + k0;
    unsigned x1 = m1 + k1;
#define TF_R(r) { x0 += x1; x1 = rotl32(x1, (r)) ^ x0; }
    TF_R(13) TF_R(15) TF_R(26) TF_R(6)
    x0 += k1;  x1 += ks2 + 1u;
    TF_R(17) TF_R(29) TF_R(16) TF_R(24)
    x0 += ks2; x1 += k0 + 2u;
    TF_R(13) TF_R(15) TF_R(26) TF_R(6)
    x0 += k0;  x1 += k1 + 3u;
    TF_R(17) TF_R(29) TF_R(16) TF_R(24)
    x0 += k1;  x1 += ks2 + 4u;
    TF_R(13) TF_R(15) TF_R(26) TF_R(6)
    x0 += ks2; x1 += k0 + 5u;
#undef TF_R
    o0 = x0; o1 = x1;
}

__device__ __forceinline__ unsigned jax_bits32(unsigned ka, unsigned kb, unsigned i) {
    unsigned o0, o1;
    threefry2x32(ka, kb, 0u, i, o0, o1);
    return o0 ^ o1;
}

// JAX gumbel: u = bitcast((bits>>9)|0x3f800000)-1; f = max(tiny, u*(1-tiny)+tiny)
// ((1-tiny) rounds to 1.0f); g = -log(-log(f)). libdevice logf == XLA's log.
__device__ __forceinline__ float gumbel_from_bits(unsigned bits) {
    float u = __uint_as_float(0x3f800000u | (bits >> 9)) - 1.0f;
    float f = fmaxf(TINYF, u + TINYF);
    return -logf(-logf(f));
}

// Aux kernel: 1 block. warp0 = structure/sequence swap detect; remaining
// threads tabulate la/lm over the alpha table (nA <= TMAX_TAB entries).
__global__ void aux_kernel(const int* __restrict__ pA, const int* __restrict__ pB,
                           const float* __restrict__ alpha, int nA)
{
    int tid = threadIdx.x;
    if (tid < 32) {
        int v = (tid < 16) ? pA[tid] : pB[tid - 16];
        unsigned big = __ballot_sync(0xffffffffu, v > 32);
        if (tid == 0) g_swap = ((big & 0xFFFFu) == 0u) ? 1 : 0;
    }
    for (int i = tid - 32; i < nA; i += (int)blockDim.x - 32) {
        if (i >= 0) {
            float a = alpha[i];
            g_la[i] = logf(a + EPSF);
            g_lm[i] = logf((1.0f - a) + EPSF);
        }
    }
}

__device__ __forceinline__ float process_elem(
    int j, const int* __restrict__ structure, const int* __restrict__ sequence,
    const int* __restrict__ t,
    unsigned ksa, unsigned ksb, unsigned kqa, unsigned kqb,
    int rows, int shift, int L)
{
    int r, x0, N, MASK;
    unsigned ka, kb;
    if (j < rows) {
        r = j; x0 = structure[j]; N = 516; MASK = 3; ka = ksa; kb = ksb;
    } else if (j < 2 * rows) {
        r = j - rows; x0 = sequence[r]; N = 33; MASK = 32; ka = kqa; kb = kqb;
    } else {
        return (float)t[j - 2 * rows];
    }

    if (x0 == MASK) return (float)x0;   // combined channel always wins

    int batch = (shift >= 0) ? (r >> shift) : (r / L);
    int tv    = t[batch];
    float la  = g_la[tv];
    float lm  = g_lm[tv];

    unsigned base = (unsigned)r * (unsigned)N;
    unsigned b1 = jax_bits32(ka, kb, base + (unsigned)x0);
    unsigned b2 = jax_bits32(ka, kb, base + (unsigned)MASK);
    float vx = gumbel_from_bits(b1) + la;
    float vm = gumbel_from_bits(b2) + lm;
    if (vx > vm) return (float)x0;
    if (vm > vx) return (float)MASK;
    return (float)((x0 < MASK) ? x0 : MASK);   // argmax first-max tie-break
}

__global__ __launch_bounds__(256)
void d3pm_main_kernel(const int* __restrict__ pA, const int* __restrict__ pB,
                      const int* __restrict__ t,
                      float* __restrict__ out,
                      unsigned ksa, unsigned ksb,
                      unsigned kqa, unsigned kqb,
                      int rows, int total, int shift, int L)
{
    const int swap = g_swap;
    const int* structure = swap ? pB : pA;
    const int* sequence  = swap ? pA : pB;

    int g = blockIdx.x * blockDim.x + threadIdx.x;
    int j = 2 * g;
    if (j >= total) return;

    float v0 = process_elem(j, structure, sequence, t,
                            ksa, ksb, kqa, kqb, rows, shift, L);
    if (j + 1 < total) {
        float v1 = process_elem(j + 1, structure, sequence, t,
                                ksa, ksb, kqa, kqb, rows, shift, L);
        // j even -> 8-byte aligned float2 store
        *reinterpret_cast<float2*>(out + j) = make_float2(v0, v1);
    } else {
        out[j] = v0;
    }
}

extern "C" void kernel_launch(void* const* d_in, const int* in_sizes, int n_in,
                              void* d_out, int out_size)
{
    // Bind by size: two largest (equal) = structure/sequence candidates
    // (disambiguated on-device); of the two small ones, t's size divides
    // rows while alpha's (T+1 = 501) does not.
    int idx[4] = {0, 1, 2, 3};
    for (int i = 0; i < 3; i++)
        for (int k = i + 1; k < 4; k++)
            if (in_sizes[idx[k]] > in_sizes[idx[i]]) {
                int tmp = idx[i]; idx[i] = idx[k]; idx[k] = tmp;
            }
    const int iA = idx[0], iB = idx[1];
    int iT = idx[3], iAl = idx[2];
    const int rows = in_sizes[iA];
    if (rows % in_sizes[iT] != 0 && rows % in_sizes[iAl] == 0) {
        int tmp = iT; iT = iAl; iAl = tmp;
    }

    const int*   pA    = (const int*)  d_in[iA];
    const int*   pB    = (const int*)  d_in[iB];
    const int*   t     = (const int*)  d_in[iT];
    const float* alpha = (const float*)d_in[iAl];
    const int    Bv    = in_sizes[iT];
    const int    L     = rows / Bv;
    int nA = in_sizes[iAl]; if (nA > TMAX_TAB) nA = TMAX_TAB;

    int shift = -1;
    if ((L & (L - 1)) == 0) { shift = 0; while ((1 << shift) < L) shift++; }

    // key = jax.random.key(42) -> (0, 42)
    // partitionable (foldlike) split: key_i = (o0, o1) of F((0,42), (0, i))
    unsigned ksa, ksb, kqa, kqb;
    threefry2x32(0u, 42u, 0u, 0u, ksa, ksb);   // ks (structure)
    threefry2x32(0u, 42u, 0u, 1u, kqa, kqb);   // kq (sequence)

    aux_kernel<<<1, 544>>>(pA, pB, alpha, nA);

    const int total   = 2 * rows + Bv;
    const int pairs   = (total + 1) / 2;
    const int blocks  = (pairs + 255) / 256;

    d3pm_main_kernel<<<blocks, 256>>>(
        pA, pB, t, (float*)d_out,
        ksa, ksb, kqa, kqb, rows, total, shift, L);
}

// round 12
// speedup vs baseline: 1.5552x; 1.1628x over previous
#include <cuda_runtime.h>
#include <cstdint>

// D3PM q_sample — bit-exact vs JAX threefry, partitionable mode:
//   split:  key_i = (o0, o1) of threefry2x32((0,42), (0, i))     [foldlike]
//   bits32: bits[i] = o0 ^ o1 of threefry2x32(key, (0, flat_idx)),
//           flat_idx row-major over (B, L, N).
//
// Output (float32): [0,R) noised_structure, [R,2R) noised_sequence, [2R,2R+B) t.
//
// Pruning theorem (exact): argmax of gumbel+logits is ALWAYS x0 or MASK, so 2
// RNG draws per element suffice. Ties -> lower class index. Compare path is
// bit-identical to the reference (a single flipped token already exceeds the
// 1e-3 rel-err budget, so no approximate shortcut is admissible).
//
// R10/R11 lessons baked in: ONE kernel, NO barriers, no cross-kernel tables.
//  - structure/sequence disambiguation: per-warp ballot on 16 elems of each
//    (sequence <= 32 always; structure exceeds 32 w.p. 1-8e-20). Broadcast
//    loads, warp-uniform result, no sync.
//  - la/lm: per-thread logf pair AMORTIZED over 4 consecutive elements (one
//    batch per 4-group when L % 4 == 0); the t->alpha->logf chain overlaps
//    the thread's 8 independent threefry chains.
//  - int4 x0 loads + float4 stores (groups never straddle: rows % 4 == 0).

#define TINYF 1.17549435e-38f
#define EPSF  1e-10f

__host__ __device__ __forceinline__ unsigned rotl32(unsigned x, int r) {
#ifdef __CUDA_ARCH__
    return __funnelshift_l(x, x, r);
#else
    return (x << r) | (x >> (32 - r));
#endif
}

// Standard threefry2x32, 20 rounds (matches jax/_src/prng.py lowering).
__host__ __device__ __forceinline__ void threefry2x32(
    unsigned k0, unsigned k1, unsigned m0, unsigned m1,
    unsigned& o0, unsigned& o1)
{
    const unsigned ks2 = 0x1BD11BDAu ^ k0 ^ k1;
    unsigned x0 = m0 + k0;
    unsigned x1 = m1 + k1;
#define TF_R(r) { x0 += x1; x1 = rotl32(x1, (r)) ^ x0; }
    TF_R(13) TF_R(15) TF_R(26) TF_R(6)
    x0 += k1;  x1 += ks2 + 1u;
    TF_R(17) TF_R(29) TF_R(16) TF_R(24)
    x0 += ks2; x1 += k0 + 2u;
    TF_R(13) TF_R(15) TF_R(26) TF_R(6)
    x0 += k0;  x1 += k1 + 3u;
    TF_R(17) TF_R(29) TF_R(16) TF_R(24)
    x0 += k1;  x1 += ks2 + 4u;
    TF_R(13) TF_R(15) TF_R(26) TF_R(6)
    x0 += ks2; x1 += k0 + 5u;
#undef TF_R
    o0 = x0; o1 = x1;
}

__device__ __forceinline__ unsigned jax_bits32(unsigned ka, unsigned kb, unsigned i) {
    unsigned o0, o1;
    threefry2x32(ka, kb, 0u, i, o0, o1);
    return o0 ^ o1;
}

// JAX gumbel: u = bitcast((bits>>9)|0x3f800000)-1; f = max(tiny, u*(1-tiny)+tiny)
// ((1-tiny) rounds to 1.0f); g = -log(-log(f)). libdevice logf == XLA's log.
__device__ __forceinline__ float gumbel_from_bits(unsigned bits) {
    float u = __uint_as_float(0x3f800000u | (bits >> 9)) - 1.0f;
    float f = fmaxf(TINYF, u + TINYF);
    return -logf(-logf(f));
}

// One element's sample given precomputed la/lm. Bit-exact compare + tie-break.
__device__ __forceinline__ float sample_one(
    int r, int x0, float la, float lm,
    unsigned ka, unsigned kb, int N, int MASK)
{
    if (x0 == MASK) return (float)x0;   // combined channel always wins
    unsigned base = (unsigned)r * (unsigned)N;
    unsigned b1 = jax_bits32(ka, kb, base + (unsigned)x0);
    unsigned b2 = jax_bits32(ka, kb, base + (unsigned)MASK);
    float vx = gumbel_from_bits(b1) + la;
    float vm = gumbel_from_bits(b2) + lm;
    if (vx > vm) return (float)x0;
    if (vm > vx) return (float)MASK;
    return (float)((x0 < MASK) ? x0 : MASK);   // argmax first-max tie-break
}

__global__ __launch_bounds__(256)
void d3pm_kernel(const int* __restrict__ pA, const int* __restrict__ pB,
                 const int* __restrict__ t, const float* __restrict__ alpha,
                 float* __restrict__ out,
                 unsigned ksa, unsigned ksb,
                 unsigned kqa, unsigned kqb,
                 int rows, int Bv, int shift, int L, int fast)
{
    // per-warp swap detect (no block sync): which big array is structure?
    int lane = threadIdx.x & 31;
    int v = (lane < 16) ? pA[lane] : pB[lane - 16];
    unsigned big = __ballot_sync(0xffffffffu, v > 32);
    const bool swap = ((big & 0xFFFFu) == 0u);
    const int* structure = swap ? pB : pA;
    const int* sequence  = swap ? pA : pB;

    const int total = 2 * rows + Bv;
    const int gt    = blockIdx.x * blockDim.x + threadIdx.x;

    if (fast) {
        // 4 elements per thread; groups are 4-aligned and never straddle
        // segment boundaries (rows % 4 == 0) nor batch boundaries (L % 4 == 0).
        int j = gt * 4;
        if (j >= total) return;

        if (j < 2 * rows) {
            const bool isS = (j < rows);
            const int  r0  = isS ? j : j - rows;
            const int  N    = isS ? 516 : 33;
            const int  MASK = isS ? 3   : 32;
            const unsigned ka = isS ? ksa : kqa;
            const unsigned kb = isS ? ksb : kqb;
            const int* src = isS ? structure : sequence;

            // one batch for the whole group -> one t/alpha load + 2 logf
            int   tv = t[r0 >> shift];
            float a  = alpha[tv];
            float la = logf(a + EPSF);
            float lm = logf((1.0f - a) + EPSF);

            int4 x = *reinterpret_cast<const int4*>(src + r0);

            float4 o;
            o.x = sample_one(r0 + 0, x.x, la, lm, ka, kb, N, MASK);
            o.y = sample_one(r0 + 1, x.y, la, lm, ka, kb, N, MASK);
            o.z = sample_one(r0 + 2, x.z, la, lm, ka, kb, N, MASK);
            o.w = sample_one(r0 + 3, x.w, la, lm, ka, kb, N, MASK);
            *reinterpret_cast<float4*>(out + j) = o;
        } else {
            // t passthrough (tiny tail; scalar)
            #pragma unroll
            for (int q = 0; q < 4; q++) {
                int jj = j + q;
                if (jj < total) out[jj] = (float)t[jj - 2 * rows];
            }
        }
    } else {
        // generic scalar fallback (any geometry)
        for (int j = gt; j < total; j += gridDim.x * blockDim.x) {
            if (j < 2 * rows) {
                const bool isS = (j < rows);
                const int  r   = isS ? j : j - rows;
                int   tv = t[(shift >= 0) ? (r >> shift) : (r / L)];
                float a  = alpha[tv];
                float la = logf(a + EPSF);
                float lm = logf((1.0f - a) + EPSF);
                if (isS) out[j] = sample_one(r, structure[r], la, lm, ksa, ksb, 516, 3);
                else     out[j] = sample_one(r, sequence[r],  la, lm, kqa, kqb, 33, 32);
            } else {
                out[j] = (float)t[j - 2 * rows];
            }
        }
    }
}

extern "C" void kernel_launch(void* const* d_in, const int* in_sizes, int n_in,
                              void* d_out, int out_size)
{
    // Bind by size: two largest (equal) = structure/sequence candidates
    // (disambiguated on-device); of the two small ones, t's size divides
    // rows while alpha's (T+1 = 501) does not.
    int idx[4] = {0, 1, 2, 3};
    for (int i = 0; i < 3; i++)
        for (int k = i + 1; k < 4; k++)
            if (in_sizes[idx[k]] > in_sizes[idx[i]]) {
                int tmp = idx[i]; idx[i] = idx[k]; idx[k] = tmp;
            }
    const int iA = idx[0], iB = idx[1];
    int iT = idx[3], iAl = idx[2];
    const int rows = in_sizes[iA];
    if (rows % in_sizes[iT] != 0 && rows % in_sizes[iAl] == 0) {
        int tmp = iT; iT = iAl; iAl = tmp;
    }

    const int*   pA    = (const int*)  d_in[iA];
    const int*   pB    = (const int*)  d_in[iB];
    const int*   t     = (const int*)  d_in[iT];
    const float* alpha = (const float*)d_in[iAl];
    const int    Bv    = in_sizes[iT];
    const int    L     = rows / Bv;

    int shift = -1;
    if ((L & (L - 1)) == 0) { shift = 0; while ((1 << shift) < L) shift++; }
    const int fast = (shift >= 0) && (L % 4 == 0) && (rows % 4 == 0);

    // key = jax.random.key(42) -> (0, 42)
    // partitionable (foldlike) split: key_i = (o0, o1) of F((0,42), (0, i))
    unsigned ksa, ksb, kqa, kqb;
    threefry2x32(0u, 42u, 0u, 0u, ksa, ksb);   // ks (structure)
    threefry2x32(0u, 42u, 0u, 1u, kqa, kqb);   // kq (sequence)

    const int total = 2 * rows + Bv;
    int blocks;
    if (fast) {
        const int groups = (total + 3) / 4;
        blocks = (groups + 255) / 256;
    } else {
        blocks = (total + 255) / 256;
        if (blocks > 2048) blocks = 2048;
    }

    d3pm_kernel<<<blocks, 256>>>(
        pA, pB, t, alpha, (float*)d_out,
        ksa, ksb, kqa, kqb, rows, Bv, shift, L, fast);
}